// round 14
// baseline (speedup 1.0000x reference)
#include <cuda_runtime.h>
#include <cuda_bf16.h>
#include <cuda_fp16.h>
#include <math.h>
#include <stdint.h>

// Problem constants
#define Bsz   16
#define Tlen  1024
#define Din   8704
#define Rdim  256
#define Hdim  72
#define G3    216     // 3*H
#define TAU   12

typedef unsigned long long u64;

// ---------------- scratch (device globals; no allocation allowed) ----------
__device__ __half g_wchi[(size_t)G3 * Din];   // combined weight (fp16)
__device__ float g_bc[G3];                    // combined bias
__device__ float g_xp[(size_t)Bsz * Tlen * G3];
__device__ float g_q[Bsz * Tlen];

// ---------------- helpers ---------------------------------------------------
__device__ __forceinline__ void upk2(u64 v, float& lo, float& hi) {
    asm("mov.b64 {%0, %1}, %2;" : "=f"(lo), "=f"(hi) : "l"(v));
}
__device__ __forceinline__ u64 fma2(u64 a, u64 b, u64 c) {
    u64 d;
    asm("fma.rn.f32x2 %0, %1, %2, %3;" : "=l"(d) : "l"(a), "l"(b), "l"(c));
    return d;
}
__device__ __forceinline__ float sigf(float v) {
    return __fdividef(1.0f, 1.0f + __expf(-v));
}
__device__ __forceinline__ float tanhfast(float v) {
    return 1.0f - __fdividef(2.0f, __expf(2.0f * v) + 1.0f);
}
// pack two fp32 into f16x2 (lower <- a, upper <- b)
__device__ __forceinline__ uint32_t f16pack(float a, float b) {
    __half2 h2 = __halves2half2(__float2half_rn(a), __float2half_rn(b));
    return *reinterpret_cast<uint32_t*>(&h2);
}
// m16n8k16 fp16 MMA, fp32 accumulate (sm_80+ PTX)
__device__ __forceinline__ void mma_f16(float* d, uint32_t a0, uint32_t a1,
                                        uint32_t a2, uint32_t a3,
                                        uint32_t b0, uint32_t b1) {
    asm volatile(
        "mma.sync.aligned.m16n8k16.row.col.f32.f16.f16.f32 "
        "{%0,%1,%2,%3}, {%4,%5,%6,%7}, {%8,%9}, {%0,%1,%2,%3};"
        : "+f"(d[0]), "+f"(d[1]), "+f"(d[2]), "+f"(d[3])
        : "r"(a0), "r"(a1), "r"(a2), "r"(a3), "r"(b0), "r"(b1));
}
__device__ __forceinline__ uint32_t smem_u32(const void* p) {
    uint32_t a;
    asm("{ .reg .u64 t; cvta.to.shared.u64 t, %1; cvt.u32.u64 %0, t; }" : "=r"(a) : "l"(p));
    return a;
}
__device__ __forceinline__ void cp_async16(uint32_t dst, const void* src) {
    asm volatile("cp.async.cg.shared.global [%0], [%1], 16;" :: "r"(dst), "l"(src));
}
#define CP_COMMIT()  asm volatile("cp.async.commit_group;" ::: "memory")
#define CP_WAIT1()   asm volatile("cp.async.wait_group 1;" ::: "memory")
#define CP_WAIT0()   asm volatile("cp.async.wait_group 0;" ::: "memory")

// ---------------- kernel: combined bias b_c = w_ih @ b_dr + b_ih -----------
__global__ void bc_kernel(const float* __restrict__ w_ih,
                          const float* __restrict__ b_dr,
                          const float* __restrict__ b_ih) {
    int g = threadIdx.x;
    if (g >= G3) return;
    float acc = b_ih[g];
    for (int r = 0; r < Rdim; r++) acc += w_ih[g * Rdim + r] * b_dr[r];
    g_bc[g] = acc;
}

// ---------------- kernel: combined weight -> fp16 ---------------------------
__global__ void __launch_bounds__(384) combine_kernel(const float* __restrict__ w_dr,
                                                      const float* __restrict__ w_ih) {
    __shared__ float sWdr[128][64];
    __shared__ float sWih[24][128];
    const int d0 = blockIdx.x * 64;
    const int g0 = blockIdx.y * 24;
    const int tid = threadIdx.x;
    const int dloc = (tid & 15) * 4;
    const int gloc = tid >> 4;

    float a0 = 0.f, a1 = 0.f, a2 = 0.f, a3 = 0.f;

    for (int r0 = 0; r0 < Rdim; r0 += 128) {
        for (int idx = tid; idx < 128 * 64; idx += 384) {
            int r = idx >> 6, d = idx & 63;
            sWdr[r][d] = w_dr[(size_t)(r0 + r) * Din + d0 + d];
        }
        for (int idx = tid; idx < 24 * 128; idx += 384) {
            int g = idx >> 7, r = idx & 127;
            sWih[g][r] = w_ih[(g0 + g) * Rdim + r0 + r];
        }
        __syncthreads();
        #pragma unroll 4
        for (int r = 0; r < 128; r++) {
            float wi = sWih[gloc][r];
            float4 wd = *reinterpret_cast<const float4*>(&sWdr[r][dloc]);
            a0 = fmaf(wi, wd.x, a0);
            a1 = fmaf(wi, wd.y, a1);
            a2 = fmaf(wi, wd.z, a2);
            a3 = fmaf(wi, wd.w, a3);
        }
        __syncthreads();
    }
    const size_t e = (size_t)(g0 + gloc) * Din + d0 + dloc;
    *reinterpret_cast<uint2*>(reinterpret_cast<char*>(g_wchi) + e * 2) =
        make_uint2(f16pack(a0, a1), f16pack(a2, a3));
}

// ---------------- kernel: HMMA GEMM  xp = x @ w_c^T + b_c (R13 verbatim) ---
#define KC       64
#define NCHUNK   (Din / KC)      // 136
#define A_ST_SZ  8192            // 64 rows x 64 k x 2B fp16
#define B_BASE   16384
#define B_ROW    144
#define B_ST_SZ  32256           // 224 rows x 144B
#define BIAS_OFF2 (B_BASE + 3 * B_ST_SZ)        // 113152
#define GEMM_SMEM (BIAS_OFF2 + 896)             // 114048

__global__ void __launch_bounds__(256, 1) gemm_hmma_kernel(const float* __restrict__ x,
                                                           const int* __restrict__ x_len) {
    extern __shared__ __align__(16) char sm[];
    const int tid = threadIdx.x;
    const int bx = blockIdx.x;
    const int batch = bx & 15;
    const int tile = bx >> 4;
    const int m0 = batch * Tlen + tile * 64;
    if (tile * 64 >= x_len[batch]) return;

    const uint32_t sb = smem_u32(sm);
    if (tid < G3) *reinterpret_cast<float*>(sm + BIAS_OFF2 + tid * 4) = g_bc[tid];

    const int ar = tid >> 2, aq = tid & 3;
    const float* asrc = x + (size_t)(m0 + ar) * Din + aq * 16;
    const uint32_t aSt = (uint32_t)(aq * 2048 + (ar >> 3) * 256 + (ar & 7) * 32);

    uint32_t bDst[7];
    const char* bSrc[7];
    #pragma unroll
    for (int i = 0; i < 7; i++) {
        const int task = tid + i * 256;
        const int row = task >> 3, seg = task & 7;
        const int rs = (row < G3) ? row : (G3 - 1);
        bDst[i] = sb + B_BASE + (uint32_t)(row * B_ROW + seg * 16);
        bSrc[i] = (const char*)g_wchi + (size_t)rs * (Din * 2) + seg * 16;
    }

    const int wid = tid >> 5;
    const int lane = tid & 31;
    const int wm = wid >> 2;
    const int wn = wid & 3;

    float acc[2][7][4];
    #pragma unroll
    for (int f = 0; f < 2; f++)
        #pragma unroll
        for (int j = 0; j < 7; j++)
            #pragma unroll
            for (int c = 0; c < 4; c++) acc[f][j][c] = 0.f;

    float4 av[4];

    #define STORE_A(dstbase) do {                                               \
        uint32_t H[8];                                                          \
        H[0] = f16pack(av[0].x, av[0].y);                                       \
        H[1] = f16pack(av[0].z, av[0].w);                                       \
        H[2] = f16pack(av[1].x, av[1].y);                                       \
        H[3] = f16pack(av[1].z, av[1].w);                                       \
        H[4] = f16pack(av[2].x, av[2].y);                                       \
        H[5] = f16pack(av[2].z, av[2].w);                                       \
        H[6] = f16pack(av[3].x, av[3].y);                                       \
        H[7] = f16pack(av[3].z, av[3].w);                                       \
        char* pa = (dstbase) + aSt;                                             \
        _Pragma("unroll")                                                       \
        for (int c = 0; c < 4; c++) {                                           \
            *reinterpret_cast<uint2*>(pa + c * 8) = make_uint2(H[c], H[c + 4]); \
        }                                                                       \
    } while (0)

    #pragma unroll
    for (int i = 0; i < 7; i++) cp_async16(bDst[i], bSrc[i]);
    CP_COMMIT();
    #pragma unroll
    for (int i = 0; i < 7; i++) cp_async16(bDst[i] + B_ST_SZ, bSrc[i] + 128);
    CP_COMMIT();
    {
        av[0] = __ldg((const float4*)(asrc + 0));
        av[1] = __ldg((const float4*)(asrc + 4));
        av[2] = __ldg((const float4*)(asrc + 8));
        av[3] = __ldg((const float4*)(asrc + 12));
        STORE_A(sm);
    }
    CP_WAIT1();
    __syncthreads();

    for (int ck = 0; ck < NCHUNK; ck++) {
        const int sA = ck & 1;
        const int sB = ck % 3;
        const bool more = (ck + 1 < NCHUNK);
        const bool more2 = (ck + 2 < NCHUNK);

        if (more2) {
            const int sB2 = (ck + 2) % 3;
            const size_t go = (size_t)(ck + 2) * 128;
            #pragma unroll
            for (int i = 0; i < 7; i++)
                cp_async16(bDst[i] + (uint32_t)(sB2 * B_ST_SZ), bSrc[i] + go);
            CP_COMMIT();
        }
        if (more) {
            const int koff = (ck + 1) * KC;
            av[0] = __ldg((const float4*)(asrc + koff + 0));
            av[1] = __ldg((const float4*)(asrc + koff + 4));
            av[2] = __ldg((const float4*)(asrc + koff + 8));
            av[3] = __ldg((const float4*)(asrc + koff + 12));
        }

        const char* ast = sm + sA * A_ST_SZ;
        const char* bst = sm + B_BASE + sB * B_ST_SZ;
        #pragma unroll
        for (int kb = 0; kb < 4; kb++) {
            const char* pa = ast + kb * 2048 + wm * 1024 + lane * 8;
            uint2 Ah[4];
            #pragma unroll
            for (int i = 0; i < 4; i++)
                Ah[i] = *reinterpret_cast<const uint2*>(pa + i * 256);
            uint32_t Bh0[7], Bh1[7];
            #pragma unroll
            for (int j = 0; j < 7; j++) {
                const uint32_t bro = (uint32_t)((wn * 56 + j * 8 + (lane >> 2)) * B_ROW
                                                + kb * 32 + (lane & 3) * 4);
                Bh0[j] = *reinterpret_cast<const uint32_t*>(bst + bro);
                Bh1[j] = *reinterpret_cast<const uint32_t*>(bst + bro + 16);
            }
            #pragma unroll
            for (int f = 0; f < 2; f++) {
                const uint32_t ah0 = Ah[2 * f].x, ah1 = Ah[2 * f + 1].x;
                const uint32_t ah2 = Ah[2 * f].y, ah3 = Ah[2 * f + 1].y;
                #pragma unroll
                for (int j = 0; j < 7; j++)
                    mma_f16(acc[f][j], ah0, ah1, ah2, ah3, Bh0[j], Bh1[j]);
            }
        }

        if (more) STORE_A(sm + (sA ^ 1) * A_ST_SZ);
        if (more2) { CP_WAIT1(); } else { CP_WAIT0(); }
        __syncthreads();
    }

    const float* sbias = reinterpret_cast<const float*>(sm + BIAS_OFF2);
    #pragma unroll
    for (int f = 0; f < 2; f++) {
        const int r0 = m0 + wm * 32 + f * 16 + (lane >> 2);
        #pragma unroll
        for (int j = 0; j < 7; j++) {
            const int n = wn * 56 + j * 8 + (lane & 3) * 2;
            if (n < G3) {
                const float2 bias = *reinterpret_cast<const float2*>(sbias + n);
                float2 o0 = make_float2(acc[f][j][0] + bias.x, acc[f][j][1] + bias.y);
                float2 o1 = make_float2(acc[f][j][2] + bias.x, acc[f][j][3] + bias.y);
                *reinterpret_cast<float2*>(g_xp + (size_t)r0 * G3 + n) = o0;
                *reinterpret_cast<float2*>(g_xp + (size_t)(r0 + 8) * G3 + n) = o1;
            }
        }
    }
    #undef STORE_A
}

// ---------------- kernel: GRU — single barrier, intra-warp gate exchange ---
// 288 threads. Warps 0..7: lanes 3u,3u+1,3u+2 hold rows i, 72+i, 144+i for
// hidden unit i = w*10+u (full 72-weight row per thread, wl[36] u64).
// Gate inputs exchanged via __shfl within the warp; lane 3u computes and
// stores h_new[i]. ONE __syncthreads per step (ping-pong h buffers).
// Warp 8 computes q[t-1] overlapped with the matvec phase.
__global__ void __launch_bounds__(288) gru_kernel(const float* __restrict__ w_hh,
                                                  const float* __restrict__ b_hh,
                                                  const float* __restrict__ w_reg,
                                                  const float* __restrict__ b_reg,
                                                  const int* __restrict__ x_len) {
    __shared__ __align__(16) float hbuf[2][72];

    const int b = blockIdx.x;
    const int tid = threadIdx.x;
    const int w = tid >> 5;
    const int lane = tid & 31;
    const int L = x_len[b];

    const int u = lane / 3;            // unit within warp
    const int j = lane - u * 3;        // 0=r, 1=z, 2=n
    const int i = w * 10 + u;          // hidden unit index
    const bool mv = (w < 8) && (lane < 30) && (i < Hdim);
    const int row = j * Hdim + i;      // gate row (valid when mv)

    // FULL 72-weight row per thread (36 u64) — this was the R11 bug (wl[18]).
    u64 wl[36];
    float bh = 0.f;
    if (mv) {
        bh = b_hh[row];
        const u64* wp = reinterpret_cast<const u64*>(w_hh + row * Hdim);
        #pragma unroll
        for (int k = 0; k < 36; k++) wl[k] = wp[k];
    } else {
        #pragma unroll
        for (int k = 0; k < 36; k++) wl[k] = 0ULL;
    }

    // q-warp (warp 8)
    float wq0 = 0.f, wq1 = 0.f, wq2 = 0.f;
    if (w == 8 && lane < 24) {
        wq0 = w_reg[3 * lane];
        wq1 = w_reg[3 * lane + 1];
        wq2 = w_reg[3 * lane + 2];
    }
    const float breg = b_reg[0];
    if (tid < 72) hbuf[0][tid] = 0.f;
    __syncthreads();

    const float* xpb = g_xp + (size_t)b * Tlen * G3;
    float xcur = mv ? xpb[row] : 0.f;
    int cur = 0;

    for (int t = 0; t < L; t++) {
        float xnxt = 0.f;
        if (mv && t + 1 < Tlen) xnxt = __ldg(xpb + (size_t)(t + 1) * G3 + row);

        float val = 0.f;
        float hold = 0.f;
        if (w < 8) {
            // identical accumulation order to the proven kernel
            const ulonglong2* hp4 = reinterpret_cast<const ulonglong2*>(hbuf[cur]);
            u64 a0 = 0ULL, a1 = 0ULL, a2 = 0ULL, a3 = 0ULL;
            #pragma unroll
            for (int k = 0; k < 18; k += 2) {
                ulonglong2 h0 = hp4[k];
                ulonglong2 h1 = hp4[k + 1];
                a0 = fma2(h0.x, wl[2 * k], a0);
                a1 = fma2(h0.y, wl[2 * k + 1], a1);
                a2 = fma2(h1.x, wl[2 * k + 2], a2);
                a3 = fma2(h1.y, wl[2 * k + 3], a3);
            }
            float l0, h0f, l1, h1f, l2, h2f, l3, h3f;
            upk2(a0, l0, h0f); upk2(a1, l1, h1f);
            upk2(a2, l2, h2f); upk2(a3, l3, h3f);
            float hp = bh + ((l0 + h0f) + (l1 + h1f)) + ((l2 + h2f) + (l3 + h3f));
            val = (j != 2) ? (xcur + hp) : hp;
            if (mv && j == 0) hold = hbuf[cur][i];
        } else if (t > 0) {
            // q[t-1] from hbuf[cur] (= h after step t-1), overlapped
            float s = 0.f;
            if (lane < 24) {
                s = hbuf[cur][3 * lane] * wq0
                  + hbuf[cur][3 * lane + 1] * wq1
                  + hbuf[cur][3 * lane + 2] * wq2;
            }
            s += __shfl_down_sync(0xffffffffu, s, 16);
            s += __shfl_down_sync(0xffffffffu, s, 8);
            s += __shfl_down_sync(0xffffffffu, s, 4);
            s += __shfl_down_sync(0xffffffffu, s, 2);
            s += __shfl_down_sync(0xffffffffu, s, 1);
            if (lane == 0) g_q[b * Tlen + (t - 1)] = s + breg;
        }

        if (w < 8) {
            const int base = lane - j;
            const float vz = __shfl_sync(0xffffffffu, val, base + 1);
            const float vn = __shfl_sync(0xffffffffu, val, base + 2);
            const float xn = __shfl_sync(0xffffffffu, xcur, base + 2);
            if (mv && j == 0) {
                const float r = sigf(val);
                const float z = sigf(vz);
                const float n = tanhfast(xn + r * vn);
                hbuf[cur ^ 1][i] = (1.0f - z) * n + z * hold;
            }
        }
        __syncthreads();

        cur ^= 1;
        xcur = xnxt;
    }

    // final q[L-1]
    if (w == 8) {
        float s = 0.f;
        if (lane < 24) {
            s = hbuf[cur][3 * lane] * wq0
              + hbuf[cur][3 * lane + 1] * wq1
              + hbuf[cur][3 * lane + 2] * wq2;
        }
        s += __shfl_down_sync(0xffffffffu, s, 16);
        s += __shfl_down_sync(0xffffffffu, s, 8);
        s += __shfl_down_sync(0xffffffffu, s, 4);
        s += __shfl_down_sync(0xffffffffu, s, 2);
        s += __shfl_down_sync(0xffffffffu, s, 1);
        if (lane == 0) g_q[b * Tlen + (L - 1)] = s + breg;
    }
    for (int tt = L + tid; tt < Tlen; tt += 288) g_q[b * Tlen + tt] = 0.f;
}

// ---------------- kernel: SITP pooling + heads -----------------------------
__global__ void __launch_bounds__(256) pool_kernel(const int* __restrict__ x_len,
                                                   const float* nw1, const float* nb1,
                                                   const float* nw2, const float* nb2,
                                                   const float* lw, const float* lb,
                                                   float* __restrict__ out) {
    __shared__ float qs[Tlen];
    __shared__ float ws[Tlen];
    __shared__ float red[256];
    const int b = blockIdx.x;
    const int tid = threadIdx.x;
    const int L = x_len[b];

    for (int i = tid; i < Tlen; i += 256) {
        float qv = g_q[b * Tlen + i];
        qs[i] = qv;
        ws[i] = (i < L) ? expf(-qv) : 0.f;
    }
    __syncthreads();

    float sum = 0.f;
    for (int t = tid; t < Tlen; t += 256) {
        if (t < L) {
            float xmin = qs[t];
            #pragma unroll
            for (int j = 1; j < TAU; j++) {
                int s = t - j;
                if (s >= 0) xmin = fminf(xmin, qs[s]);
            }
            float num = 0.f, den = 0.f;
            #pragma unroll
            for (int j = 0; j < TAU; j++) {
                int s = t + j;
                if (s < Tlen) { num += ws[s] * qs[s]; den += ws[s]; }
            }
            float y = (den > 0.f) ? num / fmaxf(den, 1e-30f) : 0.f;
            sum += 0.5f * y + 0.5f * xmin;
        }
    }
    red[tid] = sum;
    __syncthreads();
    for (int off = 128; off > 0; off >>= 1) {
        if (tid < off) red[tid] += red[tid + off];
        __syncthreads();
    }
    if (tid == 0) {
        float rel = sigf(red[0] / (float)L);
        float mapped = sigf(nw1[0] * rel + nb1[0]) * nw2[0] + nb2[0];
        float aligned = lw[0] * mapped + lb[0];
        out[b] = rel;
        out[Bsz + b] = mapped;
        out[2 * Bsz + b] = aligned;
    }
}

// ---------------- launch ----------------------------------------------------
extern "C" void kernel_launch(void* const* d_in, const int* in_sizes, int n_in,
                              void* d_out, int out_size) {
    const float* x     = (const float*)d_in[0];
    const int*   x_len = (const int*)  d_in[1];
    const float* w_dr  = (const float*)d_in[2];
    const float* b_dr  = (const float*)d_in[3];
    const float* w_ih  = (const float*)d_in[4];
    const float* w_hh  = (const float*)d_in[5];
    const float* b_ih  = (const float*)d_in[6];
    const float* b_hh  = (const float*)d_in[7];
    const float* w_reg = (const float*)d_in[8];
    const float* b_reg = (const float*)d_in[9];
    const float* nw1   = (const float*)d_in[10];
    const float* nb1   = (const float*)d_in[11];
    const float* nw2   = (const float*)d_in[12];
    const float* nb2   = (const float*)d_in[13];
    const float* lw    = (const float*)d_in[14];
    const float* lb    = (const float*)d_in[15];
    float* out = (float*)d_out;

    cudaFuncSetAttribute(gemm_hmma_kernel,
                         cudaFuncAttributeMaxDynamicSharedMemorySize, GEMM_SMEM);

    bc_kernel<<<1, 256>>>(w_ih, b_dr, b_ih);
    combine_kernel<<<dim3(Din / 64, G3 / 24), 384>>>(w_dr, w_ih);
    gemm_hmma_kernel<<<(Bsz * Tlen) / 64, 256, GEMM_SMEM>>>(x, x_len);
    gru_kernel<<<Bsz, 288>>>(w_hh, b_hh, w_reg, b_reg, x_len);
    pool_kernel<<<Bsz, 256>>>(x_len, nw1, nb1, nw2, nb2, lw, lb, out);
}

// round 15
// speedup vs baseline: 1.7664x; 1.7664x over previous
#include <cuda_runtime.h>
#include <cuda_bf16.h>
#include <cuda_fp16.h>
#include <math.h>
#include <stdint.h>

// Problem constants
#define Bsz   16
#define Tlen  1024
#define Din   8704
#define Rdim  256
#define Hdim  72
#define G3    216     // 3*H
#define TAU   12

typedef unsigned long long u64;

// ---------------- scratch (device globals; no allocation allowed) ----------
__device__ __half g_wchi[(size_t)G3 * Din];   // combined weight (fp16)
__device__ float g_bc[G3];                    // combined bias
__device__ float g_xp[(size_t)Bsz * Tlen * G3];
__device__ float g_q[Bsz * Tlen];

// ---------------- helpers ---------------------------------------------------
__device__ __forceinline__ u64 pk2(float lo, float hi) {
    u64 r;
    asm("mov.b64 %0, {%1, %2};" : "=l"(r) : "f"(lo), "f"(hi));
    return r;
}
__device__ __forceinline__ void upk2(u64 v, float& lo, float& hi) {
    asm("mov.b64 {%0, %1}, %2;" : "=f"(lo), "=f"(hi) : "l"(v));
}
__device__ __forceinline__ u64 fma2(u64 a, u64 b, u64 c) {
    u64 d;
    asm("fma.rn.f32x2 %0, %1, %2, %3;" : "=l"(d) : "l"(a), "l"(b), "l"(c));
    return d;
}
__device__ __forceinline__ u64 dupf(float v) {
    u64 r;
    asm("mov.b64 %0, {%1, %1};" : "=l"(r) : "f"(v));
    return r;
}
__device__ __forceinline__ float sigf(float v) {
    return __fdividef(1.0f, 1.0f + __expf(-v));
}
__device__ __forceinline__ float tanhfast(float v) {
    return 1.0f - __fdividef(2.0f, __expf(2.0f * v) + 1.0f);
}
// pack two fp32 into f16x2 (lower <- a, upper <- b)
__device__ __forceinline__ uint32_t f16pack(float a, float b) {
    __half2 h2 = __halves2half2(__float2half_rn(a), __float2half_rn(b));
    return *reinterpret_cast<uint32_t*>(&h2);
}
// m16n8k16 fp16 MMA, fp32 accumulate (sm_80+ PTX)
__device__ __forceinline__ void mma_f16(float* d, uint32_t a0, uint32_t a1,
                                        uint32_t a2, uint32_t a3,
                                        uint32_t b0, uint32_t b1) {
    asm volatile(
        "mma.sync.aligned.m16n8k16.row.col.f32.f16.f16.f32 "
        "{%0,%1,%2,%3}, {%4,%5,%6,%7}, {%8,%9}, {%0,%1,%2,%3};"
        : "+f"(d[0]), "+f"(d[1]), "+f"(d[2]), "+f"(d[3])
        : "r"(a0), "r"(a1), "r"(a2), "r"(a3), "r"(b0), "r"(b1));
}
__device__ __forceinline__ uint32_t smem_u32(const void* p) {
    uint32_t a;
    asm("{ .reg .u64 t; cvta.to.shared.u64 t, %1; cvt.u32.u64 %0, t; }" : "=r"(a) : "l"(p));
    return a;
}
__device__ __forceinline__ void cp_async16(uint32_t dst, const void* src) {
    asm volatile("cp.async.cg.shared.global [%0], [%1], 16;" :: "r"(dst), "l"(src));
}
#define CP_COMMIT()  asm volatile("cp.async.commit_group;" ::: "memory")
#define CP_WAIT1()   asm volatile("cp.async.wait_group 1;" ::: "memory")
#define CP_WAIT0()   asm volatile("cp.async.wait_group 0;" ::: "memory")

// ---------------- kernel: combined bias b_c = w_ih @ b_dr + b_ih -----------
__global__ void bc_kernel(const float* __restrict__ w_ih,
                          const float* __restrict__ b_dr,
                          const float* __restrict__ b_ih) {
    int g = threadIdx.x;
    if (g >= G3) return;
    float acc = b_ih[g];
    for (int r = 0; r < Rdim; r++) acc += w_ih[g * Rdim + r] * b_dr[r];
    g_bc[g] = acc;
}

// ---------------- kernel: combined weight -> fp16 (fma2 inner loop) --------
__global__ void __launch_bounds__(384) combine_kernel(const float* __restrict__ w_dr,
                                                      const float* __restrict__ w_ih) {
    __shared__ float sWdr[128][64];
    __shared__ float sWih[24][128];
    const int d0 = blockIdx.x * 64;
    const int g0 = blockIdx.y * 24;
    const int tid = threadIdx.x;
    const int dloc = (tid & 15) * 4;
    const int gloc = tid >> 4;

    u64 acc01 = 0ULL, acc23 = 0ULL;

    for (int r0 = 0; r0 < Rdim; r0 += 128) {
        for (int idx = tid; idx < 128 * 64; idx += 384) {
            int r = idx >> 6, d = idx & 63;
            sWdr[r][d] = w_dr[(size_t)(r0 + r) * Din + d0 + d];
        }
        for (int idx = tid; idx < 24 * 128; idx += 384) {
            int g = idx >> 7, r = idx & 127;
            sWih[g][r] = w_ih[(g0 + g) * Rdim + r0 + r];
        }
        __syncthreads();
        #pragma unroll 4
        for (int r = 0; r < 128; r++) {
            const u64 wi2 = dupf(sWih[gloc][r]);
            const ulonglong2 wd = *reinterpret_cast<const ulonglong2*>(&sWdr[r][dloc]);
            acc01 = fma2(wi2, wd.x, acc01);
            acc23 = fma2(wi2, wd.y, acc23);
        }
        __syncthreads();
    }
    float a0, a1, a2, a3;
    upk2(acc01, a0, a1);
    upk2(acc23, a2, a3);
    const size_t e = (size_t)(g0 + gloc) * Din + d0 + dloc;
    *reinterpret_cast<uint2*>(reinterpret_cast<char*>(g_wchi) + e * 2) =
        make_uint2(f16pack(a0, a1), f16pack(a2, a3));
}

// ---------------- kernel: HMMA GEMM  xp = x @ w_c^T + b_c (R13 verbatim) ---
#define KC       64
#define NCHUNK   (Din / KC)      // 136
#define A_ST_SZ  8192            // 64 rows x 64 k x 2B fp16
#define B_BASE   16384
#define B_ROW    144
#define B_ST_SZ  32256           // 224 rows x 144B
#define BIAS_OFF2 (B_BASE + 3 * B_ST_SZ)        // 113152
#define GEMM_SMEM (BIAS_OFF2 + 896)             // 114048

__global__ void __launch_bounds__(256, 1) gemm_hmma_kernel(const float* __restrict__ x,
                                                           const int* __restrict__ x_len) {
    extern __shared__ __align__(16) char sm[];
    const int tid = threadIdx.x;
    const int bx = blockIdx.x;
    const int batch = bx & 15;
    const int tile = bx >> 4;
    const int m0 = batch * Tlen + tile * 64;
    if (tile * 64 >= x_len[batch]) return;

    const uint32_t sb = smem_u32(sm);
    if (tid < G3) *reinterpret_cast<float*>(sm + BIAS_OFF2 + tid * 4) = g_bc[tid];

    const int ar = tid >> 2, aq = tid & 3;
    const float* asrc = x + (size_t)(m0 + ar) * Din + aq * 16;
    const uint32_t aSt = (uint32_t)(aq * 2048 + (ar >> 3) * 256 + (ar & 7) * 32);

    uint32_t bDst[7];
    const char* bSrc[7];
    #pragma unroll
    for (int i = 0; i < 7; i++) {
        const int task = tid + i * 256;
        const int row = task >> 3, seg = task & 7;
        const int rs = (row < G3) ? row : (G3 - 1);
        bDst[i] = sb + B_BASE + (uint32_t)(row * B_ROW + seg * 16);
        bSrc[i] = (const char*)g_wchi + (size_t)rs * (Din * 2) + seg * 16;
    }

    const int wid = tid >> 5;
    const int lane = tid & 31;
    const int wm = wid >> 2;
    const int wn = wid & 3;

    float acc[2][7][4];
    #pragma unroll
    for (int f = 0; f < 2; f++)
        #pragma unroll
        for (int j = 0; j < 7; j++)
            #pragma unroll
            for (int c = 0; c < 4; c++) acc[f][j][c] = 0.f;

    float4 av[4];

    #define STORE_A(dstbase) do {                                               \
        uint32_t H[8];                                                          \
        H[0] = f16pack(av[0].x, av[0].y);                                       \
        H[1] = f16pack(av[0].z, av[0].w);                                       \
        H[2] = f16pack(av[1].x, av[1].y);                                       \
        H[3] = f16pack(av[1].z, av[1].w);                                       \
        H[4] = f16pack(av[2].x, av[2].y);                                       \
        H[5] = f16pack(av[2].z, av[2].w);                                       \
        H[6] = f16pack(av[3].x, av[3].y);                                       \
        H[7] = f16pack(av[3].z, av[3].w);                                       \
        char* pa = (dstbase) + aSt;                                             \
        _Pragma("unroll")                                                       \
        for (int c = 0; c < 4; c++) {                                           \
            *reinterpret_cast<uint2*>(pa + c * 8) = make_uint2(H[c], H[c + 4]); \
        }                                                                       \
    } while (0)

    #pragma unroll
    for (int i = 0; i < 7; i++) cp_async16(bDst[i], bSrc[i]);
    CP_COMMIT();
    #pragma unroll
    for (int i = 0; i < 7; i++) cp_async16(bDst[i] + B_ST_SZ, bSrc[i] + 128);
    CP_COMMIT();
    {
        av[0] = __ldg((const float4*)(asrc + 0));
        av[1] = __ldg((const float4*)(asrc + 4));
        av[2] = __ldg((const float4*)(asrc + 8));
        av[3] = __ldg((const float4*)(asrc + 12));
        STORE_A(sm);
    }
    CP_WAIT1();
    __syncthreads();

    for (int ck = 0; ck < NCHUNK; ck++) {
        const int sA = ck & 1;
        const int sB = ck % 3;
        const bool more = (ck + 1 < NCHUNK);
        const bool more2 = (ck + 2 < NCHUNK);

        if (more2) {
            const int sB2 = (ck + 2) % 3;
            const size_t go = (size_t)(ck + 2) * 128;
            #pragma unroll
            for (int i = 0; i < 7; i++)
                cp_async16(bDst[i] + (uint32_t)(sB2 * B_ST_SZ), bSrc[i] + go);
            CP_COMMIT();
        }
        if (more) {
            const int koff = (ck + 1) * KC;
            av[0] = __ldg((const float4*)(asrc + koff + 0));
            av[1] = __ldg((const float4*)(asrc + koff + 4));
            av[2] = __ldg((const float4*)(asrc + koff + 8));
            av[3] = __ldg((const float4*)(asrc + koff + 12));
        }

        const char* ast = sm + sA * A_ST_SZ;
        const char* bst = sm + B_BASE + sB * B_ST_SZ;
        #pragma unroll
        for (int kb = 0; kb < 4; kb++) {
            const char* pa = ast + kb * 2048 + wm * 1024 + lane * 8;
            uint2 Ah[4];
            #pragma unroll
            for (int i = 0; i < 4; i++)
                Ah[i] = *reinterpret_cast<const uint2*>(pa + i * 256);
            uint32_t Bh0[7], Bh1[7];
            #pragma unroll
            for (int j = 0; j < 7; j++) {
                const uint32_t bro = (uint32_t)((wn * 56 + j * 8 + (lane >> 2)) * B_ROW
                                                + kb * 32 + (lane & 3) * 4);
                Bh0[j] = *reinterpret_cast<const uint32_t*>(bst + bro);
                Bh1[j] = *reinterpret_cast<const uint32_t*>(bst + bro + 16);
            }
            #pragma unroll
            for (int f = 0; f < 2; f++) {
                const uint32_t ah0 = Ah[2 * f].x, ah1 = Ah[2 * f + 1].x;
                const uint32_t ah2 = Ah[2 * f].y, ah3 = Ah[2 * f + 1].y;
                #pragma unroll
                for (int j = 0; j < 7; j++)
                    mma_f16(acc[f][j], ah0, ah1, ah2, ah3, Bh0[j], Bh1[j]);
            }
        }

        if (more) STORE_A(sm + (sA ^ 1) * A_ST_SZ);
        if (more2) { CP_WAIT1(); } else { CP_WAIT0(); }
        __syncthreads();
    }

    const float* sbias = reinterpret_cast<const float*>(sm + BIAS_OFF2);
    #pragma unroll
    for (int f = 0; f < 2; f++) {
        const int r0 = m0 + wm * 32 + f * 16 + (lane >> 2);
        #pragma unroll
        for (int j = 0; j < 7; j++) {
            const int n = wn * 56 + j * 8 + (lane & 3) * 2;
            if (n < G3) {
                const float2 bias = *reinterpret_cast<const float2*>(sbias + n);
                float2 o0 = make_float2(acc[f][j][0] + bias.x, acc[f][j][1] + bias.y);
                float2 o1 = make_float2(acc[f][j][2] + bias.x, acc[f][j][3] + bias.y);
                *reinterpret_cast<float2*>(g_xp + (size_t)r0 * G3 + n) = o0;
                *reinterpret_cast<float2*>(g_xp + (size_t)(r0 + 8) * G3 + n) = o1;
            }
        }
    }
    #undef STORE_A
}

// ---------------- kernel: GRU (FROZEN proven ~510us version) ---------------
__global__ void __launch_bounds__(256) gru_kernel(const float* __restrict__ w_hh,
                                                  const float* __restrict__ b_hh,
                                                  const float* __restrict__ w_reg,
                                                  const float* __restrict__ b_reg,
                                                  const int* __restrict__ x_len) {
    __shared__ __align__(16) float hbuf[2][72];
    __shared__ float pre[144];
    __shared__ float hpn[72];
    __shared__ float xnn[72];

    const int b = blockIdx.x;
    const int g = threadIdx.x;
    const int L = x_len[b];

    u64 wl[36];
    float bh = 0.f;
    if (g < G3) {
        bh = b_hh[g];
        const u64* wp = reinterpret_cast<const u64*>(w_hh + g * Hdim);
        #pragma unroll
        for (int k = 0; k < 36; k++) wl[k] = wp[k];
    }
    const int lane = g - 224;
    float wq0 = 0.f, wq1 = 0.f, wq2 = 0.f;
    if (g >= 224 && lane < 24) {
        wq0 = w_reg[3 * lane];
        wq1 = w_reg[3 * lane + 1];
        wq2 = w_reg[3 * lane + 2];
    }
    const float breg = b_reg[0];
    if (g < 72) hbuf[0][g] = 0.f;
    __syncthreads();

    const float* xpb = g_xp + (size_t)b * Tlen * G3;
    float xcur = (g < G3) ? xpb[g] : 0.f;
    int cur = 0;

    for (int t = 0; t < L; t++) {
        float xnxt = 0.f;
        if (g < G3 && t + 1 < Tlen) xnxt = __ldg(xpb + (size_t)(t + 1) * G3 + g);

        if (g < G3) {
            const ulonglong2* hp4 = reinterpret_cast<const ulonglong2*>(hbuf[cur]);
            u64 a0 = 0ULL, a1 = 0ULL, a2 = 0ULL, a3 = 0ULL;
            #pragma unroll
            for (int k = 0; k < 18; k += 2) {
                ulonglong2 h0 = hp4[k];
                ulonglong2 h1 = hp4[k + 1];
                a0 = fma2(h0.x, wl[2 * k], a0);
                a1 = fma2(h0.y, wl[2 * k + 1], a1);
                a2 = fma2(h1.x, wl[2 * k + 2], a2);
                a3 = fma2(h1.y, wl[2 * k + 3], a3);
            }
            float l0, h0f, l1, h1f, l2, h2f, l3, h3f;
            upk2(a0, l0, h0f); upk2(a1, l1, h1f);
            upk2(a2, l2, h2f); upk2(a3, l3, h3f);
            float hp = bh + ((l0 + h0f) + (l1 + h1f)) + ((l2 + h2f) + (l3 + h3f));
            if (g < 144) {
                pre[g] = xcur + hp;
            } else {
                hpn[g - 144] = hp;
                xnn[g - 144] = xcur;
            }
        } else if (g >= 224 && t > 0) {
            float s = 0.f;
            if (lane < 24) {
                s = hbuf[cur][3 * lane] * wq0
                  + hbuf[cur][3 * lane + 1] * wq1
                  + hbuf[cur][3 * lane + 2] * wq2;
            }
            s += __shfl_down_sync(0xffffffffu, s, 16);
            s += __shfl_down_sync(0xffffffffu, s, 8);
            s += __shfl_down_sync(0xffffffffu, s, 4);
            s += __shfl_down_sync(0xffffffffu, s, 2);
            s += __shfl_down_sync(0xffffffffu, s, 1);
            if (lane == 0) g_q[b * Tlen + (t - 1)] = s + breg;
        }
        __syncthreads();

        if (g < 72) {
            float r = sigf(pre[g]);
            float z = sigf(pre[72 + g]);
            float n = tanhfast(xnn[g] + r * hpn[g]);
            hbuf[cur ^ 1][g] = (1.0f - z) * n + z * hbuf[cur][g];
        }
        __syncthreads();

        cur ^= 1;
        xcur = xnxt;
    }

    if (g >= 224) {
        float s = 0.f;
        if (lane < 24) {
            s = hbuf[cur][3 * lane] * wq0
              + hbuf[cur][3 * lane + 1] * wq1
              + hbuf[cur][3 * lane + 2] * wq2;
        }
        s += __shfl_down_sync(0xffffffffu, s, 16);
        s += __shfl_down_sync(0xffffffffu, s, 8);
        s += __shfl_down_sync(0xffffffffu, s, 4);
        s += __shfl_down_sync(0xffffffffu, s, 2);
        s += __shfl_down_sync(0xffffffffu, s, 1);
        if (lane == 0) g_q[b * Tlen + (L - 1)] = s + breg;
    }
    for (int tt = L + g; tt < Tlen; tt += 256) g_q[b * Tlen + tt] = 0.f;
}

// ---------------- kernel: SITP pooling + heads -----------------------------
__global__ void __launch_bounds__(256) pool_kernel(const int* __restrict__ x_len,
                                                   const float* nw1, const float* nb1,
                                                   const float* nw2, const float* nb2,
                                                   const float* lw, const float* lb,
                                                   float* __restrict__ out) {
    __shared__ float qs[Tlen];
    __shared__ float ws[Tlen];
    __shared__ float red[256];
    const int b = blockIdx.x;
    const int tid = threadIdx.x;
    const int L = x_len[b];

    for (int i = tid; i < Tlen; i += 256) {
        float qv = g_q[b * Tlen + i];
        qs[i] = qv;
        ws[i] = (i < L) ? expf(-qv) : 0.f;
    }
    __syncthreads();

    float sum = 0.f;
    for (int t = tid; t < Tlen; t += 256) {
        if (t < L) {
            float xmin = qs[t];
            #pragma unroll
            for (int j = 1; j < TAU; j++) {
                int s = t - j;
                if (s >= 0) xmin = fminf(xmin, qs[s]);
            }
            float num = 0.f, den = 0.f;
            #pragma unroll
            for (int j = 0; j < TAU; j++) {
                int s = t + j;
                if (s < Tlen) { num += ws[s] * qs[s]; den += ws[s]; }
            }
            float y = (den > 0.f) ? num / fmaxf(den, 1e-30f) : 0.f;
            sum += 0.5f * y + 0.5f * xmin;
        }
    }
    red[tid] = sum;
    __syncthreads();
    for (int off = 128; off > 0; off >>= 1) {
        if (tid < off) red[tid] += red[tid + off];
        __syncthreads();
    }
    if (tid == 0) {
        float rel = sigf(red[0] / (float)L);
        float mapped = sigf(nw1[0] * rel + nb1[0]) * nw2[0] + nb2[0];
        float aligned = lw[0] * mapped + lb[0];
        out[b] = rel;
        out[Bsz + b] = mapped;
        out[2 * Bsz + b] = aligned;
    }
}

// ---------------- launch ----------------------------------------------------
extern "C" void kernel_launch(void* const* d_in, const int* in_sizes, int n_in,
                              void* d_out, int out_size) {
    const float* x     = (const float*)d_in[0];
    const int*   x_len = (const int*)  d_in[1];
    const float* w_dr  = (const float*)d_in[2];
    const float* b_dr  = (const float*)d_in[3];
    const float* w_ih  = (const float*)d_in[4];
    const float* w_hh  = (const float*)d_in[5];
    const float* b_ih  = (const float*)d_in[6];
    const float* b_hh  = (const float*)d_in[7];
    const float* w_reg = (const float*)d_in[8];
    const float* b_reg = (const float*)d_in[9];
    const float* nw1   = (const float*)d_in[10];
    const float* nb1   = (const float*)d_in[11];
    const float* nw2   = (const float*)d_in[12];
    const float* nb2   = (const float*)d_in[13];
    const float* lw    = (const float*)d_in[14];
    const float* lb    = (const float*)d_in[15];
    float* out = (float*)d_out;

    cudaFuncSetAttribute(gemm_hmma_kernel,
                         cudaFuncAttributeMaxDynamicSharedMemorySize, GEMM_SMEM);

    bc_kernel<<<1, 256>>>(w_ih, b_dr, b_ih);
    combine_kernel<<<dim3(Din / 64, G3 / 24), 384>>>(w_dr, w_ih);
    gemm_hmma_kernel<<<(Bsz * Tlen) / 64, 256, GEMM_SMEM>>>(x, x_len);
    gru_kernel<<<Bsz, 256>>>(w_hh, b_hh, w_reg, b_reg, x_len);
    pool_kernel<<<Bsz, 256>>>(x_len, nw1, nb1, nw2, nb2, lw, lb, out);
}

// round 16
// speedup vs baseline: 1.7758x; 1.0053x over previous
#include <cuda_runtime.h>
#include <cuda_bf16.h>
#include <cuda_fp16.h>
#include <math.h>
#include <stdint.h>

// Problem constants
#define Bsz   16
#define Tlen  1024
#define Din   8704
#define Rdim  256
#define Hdim  72
#define G3    216     // 3*H
#define TAU   12

typedef unsigned long long u64;

// ---------------- scratch (device globals; no allocation allowed) ----------
__device__ __half g_wchi[(size_t)G3 * Din];   // combined weight (fp16)
__device__ float g_bc[G3];                    // combined bias
__device__ float g_xp[(size_t)Bsz * Tlen * G3];
__device__ float g_q[Bsz * Tlen];

// ---------------- helpers ---------------------------------------------------
__device__ __forceinline__ void upk2(u64 v, float& lo, float& hi) {
    asm("mov.b64 {%0, %1}, %2;" : "=f"(lo), "=f"(hi) : "l"(v));
}
__device__ __forceinline__ u64 fma2(u64 a, u64 b, u64 c) {
    u64 d;
    asm("fma.rn.f32x2 %0, %1, %2, %3;" : "=l"(d) : "l"(a), "l"(b), "l"(c));
    return d;
}
__device__ __forceinline__ float sigf(float v) {
    return __fdividef(1.0f, 1.0f + __expf(-v));
}
__device__ __forceinline__ float tanhfast(float v) {
    return 1.0f - __fdividef(2.0f, __expf(2.0f * v) + 1.0f);
}
// pack two fp32 into f16x2 (lower <- a, upper <- b)
__device__ __forceinline__ uint32_t f16pack(float a, float b) {
    __half2 h2 = __halves2half2(__float2half_rn(a), __float2half_rn(b));
    return *reinterpret_cast<uint32_t*>(&h2);
}
// m16n8k16 fp16 MMA, fp32 accumulate (sm_80+ PTX)
__device__ __forceinline__ void mma_f16(float* d, uint32_t a0, uint32_t a1,
                                        uint32_t a2, uint32_t a3,
                                        uint32_t b0, uint32_t b1) {
    asm volatile(
        "mma.sync.aligned.m16n8k16.row.col.f32.f16.f16.f32 "
        "{%0,%1,%2,%3}, {%4,%5,%6,%7}, {%8,%9}, {%0,%1,%2,%3};"
        : "+f"(d[0]), "+f"(d[1]), "+f"(d[2]), "+f"(d[3])
        : "r"(a0), "r"(a1), "r"(a2), "r"(a3), "r"(b0), "r"(b1));
}
__device__ __forceinline__ uint32_t smem_u32(const void* p) {
    uint32_t a;
    asm("{ .reg .u64 t; cvta.to.shared.u64 t, %1; cvt.u32.u64 %0, t; }" : "=r"(a) : "l"(p));
    return a;
}
__device__ __forceinline__ void cp_async16(uint32_t dst, const void* src) {
    asm volatile("cp.async.cg.shared.global [%0], [%1], 16;" :: "r"(dst), "l"(src));
}
#define CP_COMMIT()  asm volatile("cp.async.commit_group;" ::: "memory")
#define CP_WAIT1()   asm volatile("cp.async.wait_group 1;" ::: "memory")
#define CP_WAIT0()   asm volatile("cp.async.wait_group 0;" ::: "memory")

// ---------------- kernel: combined bias b_c = w_ih @ b_dr + b_ih -----------
__global__ void bc_kernel(const float* __restrict__ w_ih,
                          const float* __restrict__ b_dr,
                          const float* __restrict__ b_ih) {
    int g = threadIdx.x;
    if (g >= G3) return;
    float acc = b_ih[g];
    for (int r = 0; r < Rdim; r++) acc += w_ih[g * Rdim + r] * b_dr[r];
    g_bc[g] = acc;
}

// ---------------- kernel: combined weight -> fp16 ---------------------------
__global__ void __launch_bounds__(384) combine_kernel(const float* __restrict__ w_dr,
                                                      const float* __restrict__ w_ih) {
    __shared__ float sWdr[128][64];
    __shared__ float sWih[24][128];
    const int d0 = blockIdx.x * 64;
    const int g0 = blockIdx.y * 24;
    const int tid = threadIdx.x;
    const int dloc = (tid & 15) * 4;
    const int gloc = tid >> 4;

    float a0 = 0.f, a1 = 0.f, a2 = 0.f, a3 = 0.f;

    for (int r0 = 0; r0 < Rdim; r0 += 128) {
        for (int idx = tid; idx < 128 * 64; idx += 384) {
            int r = idx >> 6, d = idx & 63;
            sWdr[r][d] = w_dr[(size_t)(r0 + r) * Din + d0 + d];
        }
        for (int idx = tid; idx < 24 * 128; idx += 384) {
            int g = idx >> 7, r = idx & 127;
            sWih[g][r] = w_ih[(g0 + g) * Rdim + r0 + r];
        }
        __syncthreads();
        #pragma unroll 4
        for (int r = 0; r < 128; r++) {
            float wi = sWih[gloc][r];
            float4 wd = *reinterpret_cast<const float4*>(&sWdr[r][dloc]);
            a0 = fmaf(wi, wd.x, a0);
            a1 = fmaf(wi, wd.y, a1);
            a2 = fmaf(wi, wd.z, a2);
            a3 = fmaf(wi, wd.w, a3);
        }
        __syncthreads();
    }
    const size_t e = (size_t)(g0 + gloc) * Din + d0 + dloc;
    *reinterpret_cast<uint2*>(reinterpret_cast<char*>(g_wchi) + e * 2) =
        make_uint2(f16pack(a0, a1), f16pack(a2, a3));
}

// ---------------- kernel: HMMA GEMM  xp = x @ w_c^T + b_c ------------------
// fp16 single-pass (A fp16, B fp16). Block M=64 x N=216(pad 224). 8 warps
// (2m x 4n), warp tile 32x56. KC=64; A double-buffered register-staged;
// B 3-stage cp.async ring, rows padded to 144B.
#define KC       64
#define NCHUNK   (Din / KC)      // 136
#define A_ST_SZ  8192            // 64 rows x 64 k x 2B fp16
#define B_BASE   16384
#define B_ROW    144
#define B_ST_SZ  32256           // 224 rows x 144B
#define BIAS_OFF2 (B_BASE + 3 * B_ST_SZ)        // 113152
#define GEMM_SMEM (BIAS_OFF2 + 896)             // 114048

__global__ void __launch_bounds__(256, 1) gemm_hmma_kernel(const float* __restrict__ x,
                                                           const int* __restrict__ x_len) {
    extern __shared__ __align__(16) char sm[];
    const int tid = threadIdx.x;
    const int bx = blockIdx.x;
    const int batch = bx & 15;
    const int tile = bx >> 4;
    const int m0 = batch * Tlen + tile * 64;
    if (tile * 64 >= x_len[batch]) return;

    const uint32_t sb = smem_u32(sm);
    if (tid < G3) *reinterpret_cast<float*>(sm + BIAS_OFF2 + tid * 4) = g_bc[tid];

    // A writer: row ar = tid>>2, k-quarter aq = tid&3 (16 fp32 each)
    const int ar = tid >> 2, aq = tid & 3;
    const float* asrc = x + (size_t)(m0 + ar) * Din + aq * 16;
    const uint32_t aSt = (uint32_t)(aq * 2048 + (ar >> 3) * 256 + (ar & 7) * 32);

    // B cp.async: 7 tasks/thread (224 rows x 8 segs)
    uint32_t bDst[7];
    const char* bSrc[7];
    #pragma unroll
    for (int i = 0; i < 7; i++) {
        const int task = tid + i * 256;      // 0..1791
        const int row = task >> 3, seg = task & 7;
        const int rs = (row < G3) ? row : (G3 - 1);
        bDst[i] = sb + B_BASE + (uint32_t)(row * B_ROW + seg * 16);
        bSrc[i] = (const char*)g_wchi + (size_t)rs * (Din * 2) + seg * 16;
    }

    const int wid = tid >> 5;
    const int lane = tid & 31;
    const int wm = wid >> 2;
    const int wn = wid & 3;

    float acc[2][7][4];
    #pragma unroll
    for (int f = 0; f < 2; f++)
        #pragma unroll
        for (int j = 0; j < 7; j++)
            #pragma unroll
            for (int c = 0; c < 4; c++) acc[f][j][c] = 0.f;

    float4 av[4];

    #define STORE_A(dstbase) do {                                               \
        uint32_t H[8];                                                          \
        H[0] = f16pack(av[0].x, av[0].y);                                       \
        H[1] = f16pack(av[0].z, av[0].w);                                       \
        H[2] = f16pack(av[1].x, av[1].y);                                       \
        H[3] = f16pack(av[1].z, av[1].w);                                       \
        H[4] = f16pack(av[2].x, av[2].y);                                       \
        H[5] = f16pack(av[2].z, av[2].w);                                       \
        H[6] = f16pack(av[3].x, av[3].y);                                       \
        H[7] = f16pack(av[3].z, av[3].w);                                       \
        char* pa = (dstbase) + aSt;                                             \
        _Pragma("unroll")                                                       \
        for (int c = 0; c < 4; c++) {                                           \
            *reinterpret_cast<uint2*>(pa + c * 8) = make_uint2(H[c], H[c + 4]); \
        }                                                                       \
    } while (0)

    // prologue: B chunks 0,1 + A chunk 0
    #pragma unroll
    for (int i = 0; i < 7; i++) cp_async16(bDst[i], bSrc[i]);
    CP_COMMIT();
    #pragma unroll
    for (int i = 0; i < 7; i++) cp_async16(bDst[i] + B_ST_SZ, bSrc[i] + 128);
    CP_COMMIT();
    {
        av[0] = __ldg((const float4*)(asrc + 0));
        av[1] = __ldg((const float4*)(asrc + 4));
        av[2] = __ldg((const float4*)(asrc + 8));
        av[3] = __ldg((const float4*)(asrc + 12));
        STORE_A(sm);
    }
    CP_WAIT1();
    __syncthreads();

    for (int ck = 0; ck < NCHUNK; ck++) {
        const int sA = ck & 1;
        const int sB = ck % 3;
        const bool more = (ck + 1 < NCHUNK);
        const bool more2 = (ck + 2 < NCHUNK);

        if (more2) {
            const int sB2 = (ck + 2) % 3;
            const size_t go = (size_t)(ck + 2) * 128;
            #pragma unroll
            for (int i = 0; i < 7; i++)
                cp_async16(bDst[i] + (uint32_t)(sB2 * B_ST_SZ), bSrc[i] + go);
            CP_COMMIT();
        }
        if (more) {
            const int koff = (ck + 1) * KC;
            av[0] = __ldg((const float4*)(asrc + koff + 0));
            av[1] = __ldg((const float4*)(asrc + koff + 4));
            av[2] = __ldg((const float4*)(asrc + koff + 8));
            av[3] = __ldg((const float4*)(asrc + koff + 12));
        }

        const char* ast = sm + sA * A_ST_SZ;
        const char* bst = sm + B_BASE + sB * B_ST_SZ;
        #pragma unroll
        for (int kb = 0; kb < 4; kb++) {
            const char* pa = ast + kb * 2048 + wm * 1024 + lane * 8;
            uint2 Ah[4];
            #pragma unroll
            for (int i = 0; i < 4; i++)
                Ah[i] = *reinterpret_cast<const uint2*>(pa + i * 256);
            uint32_t Bh0[7], Bh1[7];
            #pragma unroll
            for (int j = 0; j < 7; j++) {
                const uint32_t bro = (uint32_t)((wn * 56 + j * 8 + (lane >> 2)) * B_ROW
                                                + kb * 32 + (lane & 3) * 4);
                Bh0[j] = *reinterpret_cast<const uint32_t*>(bst + bro);
                Bh1[j] = *reinterpret_cast<const uint32_t*>(bst + bro + 16);
            }
            #pragma unroll
            for (int f = 0; f < 2; f++) {
                const uint32_t ah0 = Ah[2 * f].x, ah1 = Ah[2 * f + 1].x;
                const uint32_t ah2 = Ah[2 * f].y, ah3 = Ah[2 * f + 1].y;
                #pragma unroll
                for (int j = 0; j < 7; j++)
                    mma_f16(acc[f][j], ah0, ah1, ah2, ah3, Bh0[j], Bh1[j]);
            }
        }

        if (more) STORE_A(sm + (sA ^ 1) * A_ST_SZ);
        if (more2) { CP_WAIT1(); } else { CP_WAIT0(); }
        __syncthreads();
    }

    const float* sbias = reinterpret_cast<const float*>(sm + BIAS_OFF2);
    #pragma unroll
    for (int f = 0; f < 2; f++) {
        const int r0 = m0 + wm * 32 + f * 16 + (lane >> 2);
        #pragma unroll
        for (int j = 0; j < 7; j++) {
            const int n = wn * 56 + j * 8 + (lane & 3) * 2;
            if (n < G3) {
                const float2 bias = *reinterpret_cast<const float2*>(sbias + n);
                float2 o0 = make_float2(acc[f][j][0] + bias.x, acc[f][j][1] + bias.y);
                float2 o1 = make_float2(acc[f][j][2] + bias.x, acc[f][j][3] + bias.y);
                *reinterpret_cast<float2*>(g_xp + (size_t)r0 * G3 + n) = o0;
                *reinterpret_cast<float2*>(g_xp + (size_t)(r0 + 8) * G3 + n) = o1;
            }
        }
    }
    #undef STORE_A
}

// ---------------- kernel: GRU (FROZEN proven ~510us version) ---------------
__global__ void __launch_bounds__(256) gru_kernel(const float* __restrict__ w_hh,
                                                  const float* __restrict__ b_hh,
                                                  const float* __restrict__ w_reg,
                                                  const float* __restrict__ b_reg,
                                                  const int* __restrict__ x_len) {
    __shared__ __align__(16) float hbuf[2][72];
    __shared__ float pre[144];
    __shared__ float hpn[72];
    __shared__ float xnn[72];

    const int b = blockIdx.x;
    const int g = threadIdx.x;
    const int L = x_len[b];

    u64 wl[36];
    float bh = 0.f;
    if (g < G3) {
        bh = b_hh[g];
        const u64* wp = reinterpret_cast<const u64*>(w_hh + g * Hdim);
        #pragma unroll
        for (int k = 0; k < 36; k++) wl[k] = wp[k];
    }
    const int lane = g - 224;
    float wq0 = 0.f, wq1 = 0.f, wq2 = 0.f;
    if (g >= 224 && lane < 24) {
        wq0 = w_reg[3 * lane];
        wq1 = w_reg[3 * lane + 1];
        wq2 = w_reg[3 * lane + 2];
    }
    const float breg = b_reg[0];
    if (g < 72) hbuf[0][g] = 0.f;
    __syncthreads();

    const float* xpb = g_xp + (size_t)b * Tlen * G3;
    float xcur = (g < G3) ? xpb[g] : 0.f;
    int cur = 0;

    for (int t = 0; t < L; t++) {
        float xnxt = 0.f;
        if (g < G3 && t + 1 < Tlen) xnxt = __ldg(xpb + (size_t)(t + 1) * G3 + g);

        if (g < G3) {
            const ulonglong2* hp4 = reinterpret_cast<const ulonglong2*>(hbuf[cur]);
            u64 a0 = 0ULL, a1 = 0ULL, a2 = 0ULL, a3 = 0ULL;
            #pragma unroll
            for (int k = 0; k < 18; k += 2) {
                ulonglong2 h0 = hp4[k];
                ulonglong2 h1 = hp4[k + 1];
                a0 = fma2(h0.x, wl[2 * k], a0);
                a1 = fma2(h0.y, wl[2 * k + 1], a1);
                a2 = fma2(h1.x, wl[2 * k + 2], a2);
                a3 = fma2(h1.y, wl[2 * k + 3], a3);
            }
            float l0, h0f, l1, h1f, l2, h2f, l3, h3f;
            upk2(a0, l0, h0f); upk2(a1, l1, h1f);
            upk2(a2, l2, h2f); upk2(a3, l3, h3f);
            float hp = bh + ((l0 + h0f) + (l1 + h1f)) + ((l2 + h2f) + (l3 + h3f));
            if (g < 144) {
                pre[g] = xcur + hp;
            } else {
                hpn[g - 144] = hp;
                xnn[g - 144] = xcur;
            }
        } else if (g >= 224 && t > 0) {
            float s = 0.f;
            if (lane < 24) {
                s = hbuf[cur][3 * lane] * wq0
                  + hbuf[cur][3 * lane + 1] * wq1
                  + hbuf[cur][3 * lane + 2] * wq2;
            }
            s += __shfl_down_sync(0xffffffffu, s, 16);
            s += __shfl_down_sync(0xffffffffu, s, 8);
            s += __shfl_down_sync(0xffffffffu, s, 4);
            s += __shfl_down_sync(0xffffffffu, s, 2);
            s += __shfl_down_sync(0xffffffffu, s, 1);
            if (lane == 0) g_q[b * Tlen + (t - 1)] = s + breg;
        }
        __syncthreads();

        if (g < 72) {
            float r = sigf(pre[g]);
            float z = sigf(pre[72 + g]);
            float n = tanhfast(xnn[g] + r * hpn[g]);
            hbuf[cur ^ 1][g] = (1.0f - z) * n + z * hbuf[cur][g];
        }
        __syncthreads();

        cur ^= 1;
        xcur = xnxt;
    }

    if (g >= 224) {
        float s = 0.f;
        if (lane < 24) {
            s = hbuf[cur][3 * lane] * wq0
              + hbuf[cur][3 * lane + 1] * wq1
              + hbuf[cur][3 * lane + 2] * wq2;
        }
        s += __shfl_down_sync(0xffffffffu, s, 16);
        s += __shfl_down_sync(0xffffffffu, s, 8);
        s += __shfl_down_sync(0xffffffffu, s, 4);
        s += __shfl_down_sync(0xffffffffu, s, 2);
        s += __shfl_down_sync(0xffffffffu, s, 1);
        if (lane == 0) g_q[b * Tlen + (L - 1)] = s + breg;
    }
    for (int tt = L + g; tt < Tlen; tt += 256) g_q[b * Tlen + tt] = 0.f;
}

// ---------------- kernel: SITP pooling + heads -----------------------------
__global__ void __launch_bounds__(256) pool_kernel(const int* __restrict__ x_len,
                                                   const float* nw1, const float* nb1,
                                                   const float* nw2, const float* nb2,
                                                   const float* lw, const float* lb,
                                                   float* __restrict__ out) {
    __shared__ float qs[Tlen];
    __shared__ float ws[Tlen];
    __shared__ float red[256];
    const int b = blockIdx.x;
    const int tid = threadIdx.x;
    const int L = x_len[b];

    for (int i = tid; i < Tlen; i += 256) {
        float qv = g_q[b * Tlen + i];
        qs[i] = qv;
        ws[i] = (i < L) ? expf(-qv) : 0.f;
    }
    __syncthreads();

    float sum = 0.f;
    for (int t = tid; t < Tlen; t += 256) {
        if (t < L) {
            float xmin = qs[t];
            #pragma unroll
            for (int j = 1; j < TAU; j++) {
                int s = t - j;
                if (s >= 0) xmin = fminf(xmin, qs[s]);
            }
            float num = 0.f, den = 0.f;
            #pragma unroll
            for (int j = 0; j < TAU; j++) {
                int s = t + j;
                if (s < Tlen) { num += ws[s] * qs[s]; den += ws[s]; }
            }
            float y = (den > 0.f) ? num / fmaxf(den, 1e-30f) : 0.f;
            sum += 0.5f * y + 0.5f * xmin;
        }
    }
    red[tid] = sum;
    __syncthreads();
    for (int off = 128; off > 0; off >>= 1) {
        if (tid < off) red[tid] += red[tid + off];
        __syncthreads();
    }
    if (tid == 0) {
        float rel = sigf(red[0] / (float)L);
        float mapped = sigf(nw1[0] * rel + nb1[0]) * nw2[0] + nb2[0];
        float aligned = lw[0] * mapped + lb[0];
        out[b] = rel;
        out[Bsz + b] = mapped;
        out[2 * Bsz + b] = aligned;
    }
}

// ---------------- launch ----------------------------------------------------
extern "C" void kernel_launch(void* const* d_in, const int* in_sizes, int n_in,
                              void* d_out, int out_size) {
    const float* x     = (const float*)d_in[0];
    const int*   x_len = (const int*)  d_in[1];
    const float* w_dr  = (const float*)d_in[2];
    const float* b_dr  = (const float*)d_in[3];
    const float* w_ih  = (const float*)d_in[4];
    const float* w_hh  = (const float*)d_in[5];
    const float* b_ih  = (const float*)d_in[6];
    const float* b_hh  = (const float*)d_in[7];
    const float* w_reg = (const float*)d_in[8];
    const float* b_reg = (const float*)d_in[9];
    const float* nw1   = (const float*)d_in[10];
    const float* nb1   = (const float*)d_in[11];
    const float* nw2   = (const float*)d_in[12];
    const float* nb2   = (const float*)d_in[13];
    const float* lw    = (const float*)d_in[14];
    const float* lb    = (const float*)d_in[15];
    float* out = (float*)d_out;

    cudaFuncSetAttribute(gemm_hmma_kernel,
                         cudaFuncAttributeMaxDynamicSharedMemorySize, GEMM_SMEM);

    bc_kernel<<<1, 256>>>(w_ih, b_dr, b_ih);
    combine_kernel<<<dim3(Din / 64, G3 / 24), 384>>>(w_dr, w_ih);
    gemm_hmma_kernel<<<(Bsz * Tlen) / 64, 256, GEMM_SMEM>>>(x, x_len);
    gru_kernel<<<Bsz, 256>>>(w_hh, b_hh, w_reg, b_reg, x_len);
    pool_kernel<<<Bsz, 256>>>(x_len, nw1, nb1, nw2, nb2, lw, lb, out);
}

// round 17
// speedup vs baseline: 1.8955x; 1.0674x over previous
#include <cuda_runtime.h>
#include <cuda_bf16.h>
#include <cuda_fp16.h>
#include <math.h>
#include <stdint.h>

// Problem constants
#define Bsz   16
#define Tlen  1024
#define Din   8704
#define Rdim  256
#define Hdim  72
#define G3    216     // 3*H
#define TAU   12

typedef unsigned long long u64;

// ---------------- scratch (device globals; no allocation allowed) ----------
__device__ __half g_wchi[(size_t)G3 * Din];   // combined weight (fp16)
__device__ float g_bc[G3];                    // combined bias
__device__ float g_xp[(size_t)Bsz * Tlen * G3];
__device__ float g_q[Bsz * Tlen];

// ---------------- helpers ---------------------------------------------------
__device__ __forceinline__ void upk2(u64 v, float& lo, float& hi) {
    asm("mov.b64 {%0, %1}, %2;" : "=f"(lo), "=f"(hi) : "l"(v));
}
__device__ __forceinline__ u64 fma2(u64 a, u64 b, u64 c) {
    u64 d;
    asm("fma.rn.f32x2 %0, %1, %2, %3;" : "=l"(d) : "l"(a), "l"(b), "l"(c));
    return d;
}
__device__ __forceinline__ float sigf(float v) {
    return __fdividef(1.0f, 1.0f + __expf(-v));
}
__device__ __forceinline__ float tanhfast(float v) {
    return 1.0f - __fdividef(2.0f, __expf(2.0f * v) + 1.0f);
}
// pack two fp32 into f16x2 (lower <- a, upper <- b)
__device__ __forceinline__ uint32_t f16pack(float a, float b) {
    __half2 h2 = __halves2half2(__float2half_rn(a), __float2half_rn(b));
    return *reinterpret_cast<uint32_t*>(&h2);
}
// m16n8k16 fp16 MMA, fp32 accumulate (sm_80+ PTX)
__device__ __forceinline__ void mma_f16(float* d, uint32_t a0, uint32_t a1,
                                        uint32_t a2, uint32_t a3,
                                        uint32_t b0, uint32_t b1) {
    asm volatile(
        "mma.sync.aligned.m16n8k16.row.col.f32.f16.f16.f32 "
        "{%0,%1,%2,%3}, {%4,%5,%6,%7}, {%8,%9}, {%0,%1,%2,%3};"
        : "+f"(d[0]), "+f"(d[1]), "+f"(d[2]), "+f"(d[3])
        : "r"(a0), "r"(a1), "r"(a2), "r"(a3), "r"(b0), "r"(b1));
}
__device__ __forceinline__ uint32_t smem_u32(const void* p) {
    uint32_t a;
    asm("{ .reg .u64 t; cvta.to.shared.u64 t, %1; cvt.u32.u64 %0, t; }" : "=r"(a) : "l"(p));
    return a;
}
__device__ __forceinline__ void cp_async16(uint32_t dst, const void* src) {
    asm volatile("cp.async.cg.shared.global [%0], [%1], 16;" :: "r"(dst), "l"(src));
}
#define CP_COMMIT()  asm volatile("cp.async.commit_group;" ::: "memory")
#define CP_WAIT1()   asm volatile("cp.async.wait_group 1;" ::: "memory")
#define CP_WAIT0()   asm volatile("cp.async.wait_group 0;" ::: "memory")

// ---------------- kernel: combined bias b_c = w_ih @ b_dr + b_ih -----------
__global__ void bc_kernel(const float* __restrict__ w_ih,
                          const float* __restrict__ b_dr,
                          const float* __restrict__ b_ih) {
    int g = threadIdx.x;
    if (g >= G3) return;
    float acc = b_ih[g];
    for (int r = 0; r < Rdim; r++) acc += w_ih[g * Rdim + r] * b_dr[r];
    g_bc[g] = acc;
}

// ---------------- kernel: combined weight via HMMA --------------------------
// w_c[216,8704] = w_ih[216,256] @ w_dr[256,8704], fp16 in / fp32 accum.
// Per block: M=216(pad 224) x N=128 d-cols, K=256 fully smem-resident.
// 8 warps: wm(2) x wn(4); warp tile 112x32 (7 m-frags x 4 n-frags).
#define CA_STRIDE 264                            // fp16 per row (528B, bank spread)
#define CB_OFF    (224 * CA_STRIDE * 2)          // 118272
#define CMB_SMEM  (CB_OFF + 128 * CA_STRIDE * 2) // 185856

__global__ void __launch_bounds__(256, 1) combine_hmma_kernel(const float* __restrict__ w_dr,
                                                              const float* __restrict__ w_ih) {
    extern __shared__ __align__(16) char cs[];
    __half* As = reinterpret_cast<__half*>(cs);            // [224][CA_STRIDE]
    __half* Bs = reinterpret_cast<__half*>(cs + CB_OFF);   // [128][CA_STRIDE]
    const int tid = threadIdx.x;
    const int d0 = blockIdx.x * 128;

    // zero-pad A rows 216..223 (k 0..255)
    for (int idx = tid; idx < 8 * 64; idx += 256) {
        const int r = 216 + (idx >> 6);
        const int k = (idx & 63) * 4;
        *reinterpret_cast<uint2*>(As + r * CA_STRIDE + k) = make_uint2(0u, 0u);
    }
    // A: w_ih [216][256] -> fp16
    for (int idx = tid; idx < 216 * 64; idx += 256) {
        const int g = idx >> 6, k = (idx & 63) * 4;
        const float4 v = __ldg(reinterpret_cast<const float4*>(w_ih + g * Rdim + k));
        *reinterpret_cast<uint2*>(As + g * CA_STRIDE + k) =
            make_uint2(f16pack(v.x, v.y), f16pack(v.z, v.w));
    }
    // B: w_dr[r][d0..d0+127] transposed -> Bs[d][r] fp16
    for (int idx = tid; idx < 256 * 32; idx += 256) {
        const int r = idx >> 5, j4 = (idx & 31) * 4;
        const float4 v = __ldg(reinterpret_cast<const float4*>(w_dr + (size_t)r * Din + d0 + j4));
        Bs[(j4 + 0) * CA_STRIDE + r] = __float2half_rn(v.x);
        Bs[(j4 + 1) * CA_STRIDE + r] = __float2half_rn(v.y);
        Bs[(j4 + 2) * CA_STRIDE + r] = __float2half_rn(v.z);
        Bs[(j4 + 3) * CA_STRIDE + r] = __float2half_rn(v.w);
    }
    __syncthreads();

    const int wid = tid >> 5, lane = tid & 31;
    const int wm = wid >> 2;        // 0..1 -> M offset wm*112
    const int wn = wid & 3;         // 0..3 -> N offset wn*32
    const int lr = lane >> 2;       // 0..7
    const int lc = (lane & 3) * 2;  // 0,2,4,6

    float acc[7][4][4];
    #pragma unroll
    for (int mf = 0; mf < 7; mf++)
        #pragma unroll
        for (int nf = 0; nf < 4; nf++)
            #pragma unroll
            for (int c = 0; c < 4; c++) acc[mf][nf][c] = 0.f;

    for (int ks = 0; ks < 16; ks++) {
        const int k0 = ks * 16;
        uint32_t b0[4], b1[4];
        #pragma unroll
        for (int nf = 0; nf < 4; nf++) {
            const __half* bp = Bs + (wn * 32 + nf * 8 + lr) * CA_STRIDE + k0 + lc;
            b0[nf] = *reinterpret_cast<const uint32_t*>(bp);
            b1[nf] = *reinterpret_cast<const uint32_t*>(bp + 8);
        }
        #pragma unroll
        for (int mf = 0; mf < 7; mf++) {
            const __half* ap = As + (wm * 112 + mf * 16 + lr) * CA_STRIDE + k0 + lc;
            const uint32_t a0 = *reinterpret_cast<const uint32_t*>(ap);
            const uint32_t a1 = *reinterpret_cast<const uint32_t*>(ap + 8 * CA_STRIDE);
            const uint32_t a2 = *reinterpret_cast<const uint32_t*>(ap + 8);
            const uint32_t a3 = *reinterpret_cast<const uint32_t*>(ap + 8 * CA_STRIDE + 8);
            #pragma unroll
            for (int nf = 0; nf < 4; nf++)
                mma_f16(acc[mf][nf], a0, a1, a2, a3, b0[nf], b1[nf]);
        }
    }

    // epilogue: fp32 accum -> fp16 pairs -> g_wchi[g][d]
    #pragma unroll
    for (int mf = 0; mf < 7; mf++) {
        const int g0r = wm * 112 + mf * 16 + lr;
        #pragma unroll
        for (int nf = 0; nf < 4; nf++) {
            const int d = d0 + wn * 32 + nf * 8 + lc;
            if (g0r < G3)
                *reinterpret_cast<uint32_t*>(reinterpret_cast<char*>(g_wchi)
                    + ((size_t)g0r * Din + d) * 2) = f16pack(acc[mf][nf][0], acc[mf][nf][1]);
            if (g0r + 8 < G3)
                *reinterpret_cast<uint32_t*>(reinterpret_cast<char*>(g_wchi)
                    + ((size_t)(g0r + 8) * Din + d) * 2) = f16pack(acc[mf][nf][2], acc[mf][nf][3]);
        }
    }
}

// ---------------- kernel: HMMA GEMM  xp = x @ w_c^T + b_c (R13 verbatim) ---
#define KC       64
#define NCHUNK   (Din / KC)      // 136
#define A_ST_SZ  8192            // 64 rows x 64 k x 2B fp16
#define B_BASE   16384
#define B_ROW    144
#define B_ST_SZ  32256           // 224 rows x 144B
#define BIAS_OFF2 (B_BASE + 3 * B_ST_SZ)        // 113152
#define GEMM_SMEM (BIAS_OFF2 + 896)             // 114048

__global__ void __launch_bounds__(256, 1) gemm_hmma_kernel(const float* __restrict__ x,
                                                           const int* __restrict__ x_len) {
    extern __shared__ __align__(16) char sm[];
    const int tid = threadIdx.x;
    const int bx = blockIdx.x;
    const int batch = bx & 15;
    const int tile = bx >> 4;
    const int m0 = batch * Tlen + tile * 64;
    if (tile * 64 >= x_len[batch]) return;

    const uint32_t sb = smem_u32(sm);
    if (tid < G3) *reinterpret_cast<float*>(sm + BIAS_OFF2 + tid * 4) = g_bc[tid];

    const int ar = tid >> 2, aq = tid & 3;
    const float* asrc = x + (size_t)(m0 + ar) * Din + aq * 16;
    const uint32_t aSt = (uint32_t)(aq * 2048 + (ar >> 3) * 256 + (ar & 7) * 32);

    uint32_t bDst[7];
    const char* bSrc[7];
    #pragma unroll
    for (int i = 0; i < 7; i++) {
        const int task = tid + i * 256;
        const int row = task >> 3, seg = task & 7;
        const int rs = (row < G3) ? row : (G3 - 1);
        bDst[i] = sb + B_BASE + (uint32_t)(row * B_ROW + seg * 16);
        bSrc[i] = (const char*)g_wchi + (size_t)rs * (Din * 2) + seg * 16;
    }

    const int wid = tid >> 5;
    const int lane = tid & 31;
    const int wm = wid >> 2;
    const int wn = wid & 3;

    float acc[2][7][4];
    #pragma unroll
    for (int f = 0; f < 2; f++)
        #pragma unroll
        for (int j = 0; j < 7; j++)
            #pragma unroll
            for (int c = 0; c < 4; c++) acc[f][j][c] = 0.f;

    float4 av[4];

    #define STORE_A(dstbase) do {                                               \
        uint32_t H[8];                                                          \
        H[0] = f16pack(av[0].x, av[0].y);                                       \
        H[1] = f16pack(av[0].z, av[0].w);                                       \
        H[2] = f16pack(av[1].x, av[1].y);                                       \
        H[3] = f16pack(av[1].z, av[1].w);                                       \
        H[4] = f16pack(av[2].x, av[2].y);                                       \
        H[5] = f16pack(av[2].z, av[2].w);                                       \
        H[6] = f16pack(av[3].x, av[3].y);                                       \
        H[7] = f16pack(av[3].z, av[3].w);                                       \
        char* pa = (dstbase) + aSt;                                             \
        _Pragma("unroll")                                                       \
        for (int c = 0; c < 4; c++) {                                           \
            *reinterpret_cast<uint2*>(pa + c * 8) = make_uint2(H[c], H[c + 4]); \
        }                                                                       \
    } while (0)

    #pragma unroll
    for (int i = 0; i < 7; i++) cp_async16(bDst[i], bSrc[i]);
    CP_COMMIT();
    #pragma unroll
    for (int i = 0; i < 7; i++) cp_async16(bDst[i] + B_ST_SZ, bSrc[i] + 128);
    CP_COMMIT();
    {
        av[0] = __ldg((const float4*)(asrc + 0));
        av[1] = __ldg((const float4*)(asrc + 4));
        av[2] = __ldg((const float4*)(asrc + 8));
        av[3] = __ldg((const float4*)(asrc + 12));
        STORE_A(sm);
    }
    CP_WAIT1();
    __syncthreads();

    for (int ck = 0; ck < NCHUNK; ck++) {
        const int sA = ck & 1;
        const int sB = ck % 3;
        const bool more = (ck + 1 < NCHUNK);
        const bool more2 = (ck + 2 < NCHUNK);

        if (more2) {
            const int sB2 = (ck + 2) % 3;
            const size_t go = (size_t)(ck + 2) * 128;
            #pragma unroll
            for (int i = 0; i < 7; i++)
                cp_async16(bDst[i] + (uint32_t)(sB2 * B_ST_SZ), bSrc[i] + go);
            CP_COMMIT();
        }
        if (more) {
            const int koff = (ck + 1) * KC;
            av[0] = __ldg((const float4*)(asrc + koff + 0));
            av[1] = __ldg((const float4*)(asrc + koff + 4));
            av[2] = __ldg((const float4*)(asrc + koff + 8));
            av[3] = __ldg((const float4*)(asrc + koff + 12));
        }

        const char* ast = sm + sA * A_ST_SZ;
        const char* bst = sm + B_BASE + sB * B_ST_SZ;
        #pragma unroll
        for (int kb = 0; kb < 4; kb++) {
            const char* pa = ast + kb * 2048 + wm * 1024 + lane * 8;
            uint2 Ah[4];
            #pragma unroll
            for (int i = 0; i < 4; i++)
                Ah[i] = *reinterpret_cast<const uint2*>(pa + i * 256);
            uint32_t Bh0[7], Bh1[7];
            #pragma unroll
            for (int j = 0; j < 7; j++) {
                const uint32_t bro = (uint32_t)((wn * 56 + j * 8 + (lane >> 2)) * B_ROW
                                                + kb * 32 + (lane & 3) * 4);
                Bh0[j] = *reinterpret_cast<const uint32_t*>(bst + bro);
                Bh1[j] = *reinterpret_cast<const uint32_t*>(bst + bro + 16);
            }
            #pragma unroll
            for (int f = 0; f < 2; f++) {
                const uint32_t ah0 = Ah[2 * f].x, ah1 = Ah[2 * f + 1].x;
                const uint32_t ah2 = Ah[2 * f].y, ah3 = Ah[2 * f + 1].y;
                #pragma unroll
                for (int j = 0; j < 7; j++)
                    mma_f16(acc[f][j], ah0, ah1, ah2, ah3, Bh0[j], Bh1[j]);
            }
        }

        if (more) STORE_A(sm + (sA ^ 1) * A_ST_SZ);
        if (more2) { CP_WAIT1(); } else { CP_WAIT0(); }
        __syncthreads();
    }

    const float* sbias = reinterpret_cast<const float*>(sm + BIAS_OFF2);
    #pragma unroll
    for (int f = 0; f < 2; f++) {
        const int r0 = m0 + wm * 32 + f * 16 + (lane >> 2);
        #pragma unroll
        for (int j = 0; j < 7; j++) {
            const int n = wn * 56 + j * 8 + (lane & 3) * 2;
            if (n < G3) {
                const float2 bias = *reinterpret_cast<const float2*>(sbias + n);
                float2 o0 = make_float2(acc[f][j][0] + bias.x, acc[f][j][1] + bias.y);
                float2 o1 = make_float2(acc[f][j][2] + bias.x, acc[f][j][3] + bias.y);
                *reinterpret_cast<float2*>(g_xp + (size_t)r0 * G3 + n) = o0;
                *reinterpret_cast<float2*>(g_xp + (size_t)(r0 + 8) * G3 + n) = o1;
            }
        }
    }
    #undef STORE_A
}

// ---------------- kernel: GRU (FROZEN proven ~510us version) ---------------
__global__ void __launch_bounds__(256) gru_kernel(const float* __restrict__ w_hh,
                                                  const float* __restrict__ b_hh,
                                                  const float* __restrict__ w_reg,
                                                  const float* __restrict__ b_reg,
                                                  const int* __restrict__ x_len) {
    __shared__ __align__(16) float hbuf[2][72];
    __shared__ float pre[144];
    __shared__ float hpn[72];
    __shared__ float xnn[72];

    const int b = blockIdx.x;
    const int g = threadIdx.x;
    const int L = x_len[b];

    u64 wl[36];
    float bh = 0.f;
    if (g < G3) {
        bh = b_hh[g];
        const u64* wp = reinterpret_cast<const u64*>(w_hh + g * Hdim);
        #pragma unroll
        for (int k = 0; k < 36; k++) wl[k] = wp[k];
    }
    const int lane = g - 224;
    float wq0 = 0.f, wq1 = 0.f, wq2 = 0.f;
    if (g >= 224 && lane < 24) {
        wq0 = w_reg[3 * lane];
        wq1 = w_reg[3 * lane + 1];
        wq2 = w_reg[3 * lane + 2];
    }
    const float breg = b_reg[0];
    if (g < 72) hbuf[0][g] = 0.f;
    __syncthreads();

    const float* xpb = g_xp + (size_t)b * Tlen * G3;
    float xcur = (g < G3) ? xpb[g] : 0.f;
    int cur = 0;

    for (int t = 0; t < L; t++) {
        float xnxt = 0.f;
        if (g < G3 && t + 1 < Tlen) xnxt = __ldg(xpb + (size_t)(t + 1) * G3 + g);

        if (g < G3) {
            const ulonglong2* hp4 = reinterpret_cast<const ulonglong2*>(hbuf[cur]);
            u64 a0 = 0ULL, a1 = 0ULL, a2 = 0ULL, a3 = 0ULL;
            #pragma unroll
            for (int k = 0; k < 18; k += 2) {
                ulonglong2 h0 = hp4[k];
                ulonglong2 h1 = hp4[k + 1];
                a0 = fma2(h0.x, wl[2 * k], a0);
                a1 = fma2(h0.y, wl[2 * k + 1], a1);
                a2 = fma2(h1.x, wl[2 * k + 2], a2);
                a3 = fma2(h1.y, wl[2 * k + 3], a3);
            }
            float l0, h0f, l1, h1f, l2, h2f, l3, h3f;
            upk2(a0, l0, h0f); upk2(a1, l1, h1f);
            upk2(a2, l2, h2f); upk2(a3, l3, h3f);
            float hp = bh + ((l0 + h0f) + (l1 + h1f)) + ((l2 + h2f) + (l3 + h3f));
            if (g < 144) {
                pre[g] = xcur + hp;
            } else {
                hpn[g - 144] = hp;
                xnn[g - 144] = xcur;
            }
        } else if (g >= 224 && t > 0) {
            float s = 0.f;
            if (lane < 24) {
                s = hbuf[cur][3 * lane] * wq0
                  + hbuf[cur][3 * lane + 1] * wq1
                  + hbuf[cur][3 * lane + 2] * wq2;
            }
            s += __shfl_down_sync(0xffffffffu, s, 16);
            s += __shfl_down_sync(0xffffffffu, s, 8);
            s += __shfl_down_sync(0xffffffffu, s, 4);
            s += __shfl_down_sync(0xffffffffu, s, 2);
            s += __shfl_down_sync(0xffffffffu, s, 1);
            if (lane == 0) g_q[b * Tlen + (t - 1)] = s + breg;
        }
        __syncthreads();

        if (g < 72) {
            float r = sigf(pre[g]);
            float z = sigf(pre[72 + g]);
            float n = tanhfast(xnn[g] + r * hpn[g]);
            hbuf[cur ^ 1][g] = (1.0f - z) * n + z * hbuf[cur][g];
        }
        __syncthreads();

        cur ^= 1;
        xcur = xnxt;
    }

    if (g >= 224) {
        float s = 0.f;
        if (lane < 24) {
            s = hbuf[cur][3 * lane] * wq0
              + hbuf[cur][3 * lane + 1] * wq1
              + hbuf[cur][3 * lane + 2] * wq2;
        }
        s += __shfl_down_sync(0xffffffffu, s, 16);
        s += __shfl_down_sync(0xffffffffu, s, 8);
        s += __shfl_down_sync(0xffffffffu, s, 4);
        s += __shfl_down_sync(0xffffffffu, s, 2);
        s += __shfl_down_sync(0xffffffffu, s, 1);
        if (lane == 0) g_q[b * Tlen + (L - 1)] = s + breg;
    }
    for (int tt = L + g; tt < Tlen; tt += 256) g_q[b * Tlen + tt] = 0.f;
}

// ---------------- kernel: SITP pooling + heads -----------------------------
__global__ void __launch_bounds__(256) pool_kernel(const int* __restrict__ x_len,
                                                   const float* nw1, const float* nb1,
                                                   const float* nw2, const float* nb2,
                                                   const float* lw, const float* lb,
                                                   float* __restrict__ out) {
    __shared__ float qs[Tlen];
    __shared__ float ws[Tlen];
    __shared__ float red[256];
    const int b = blockIdx.x;
    const int tid = threadIdx.x;
    const int L = x_len[b];

    for (int i = tid; i < Tlen; i += 256) {
        float qv = g_q[b * Tlen + i];
        qs[i] = qv;
        ws[i] = (i < L) ? expf(-qv) : 0.f;
    }
    __syncthreads();

    float sum = 0.f;
    for (int t = tid; t < Tlen; t += 256) {
        if (t < L) {
            float xmin = qs[t];
            #pragma unroll
            for (int j = 1; j < TAU; j++) {
                int s = t - j;
                if (s >= 0) xmin = fminf(xmin, qs[s]);
            }
            float num = 0.f, den = 0.f;
            #pragma unroll
            for (int j = 0; j < TAU; j++) {
                int s = t + j;
                if (s < Tlen) { num += ws[s] * qs[s]; den += ws[s]; }
            }
            float y = (den > 0.f) ? num / fmaxf(den, 1e-30f) : 0.f;
            sum += 0.5f * y + 0.5f * xmin;
        }
    }
    red[tid] = sum;
    __syncthreads();
    for (int off = 128; off > 0; off >>= 1) {
        if (tid < off) red[tid] += red[tid + off];
        __syncthreads();
    }
    if (tid == 0) {
        float rel = sigf(red[0] / (float)L);
        float mapped = sigf(nw1[0] * rel + nb1[0]) * nw2[0] + nb2[0];
        float aligned = lw[0] * mapped + lb[0];
        out[b] = rel;
        out[Bsz + b] = mapped;
        out[2 * Bsz + b] = aligned;
    }
}

// ---------------- launch ----------------------------------------------------
extern "C" void kernel_launch(void* const* d_in, const int* in_sizes, int n_in,
                              void* d_out, int out_size) {
    const float* x     = (const float*)d_in[0];
    const int*   x_len = (const int*)  d_in[1];
    const float* w_dr  = (const float*)d_in[2];
    const float* b_dr  = (const float*)d_in[3];
    const float* w_ih  = (const float*)d_in[4];
    const float* w_hh  = (const float*)d_in[5];
    const float* b_ih  = (const float*)d_in[6];
    const float* b_hh  = (const float*)d_in[7];
    const float* w_reg = (const float*)d_in[8];
    const float* b_reg = (const float*)d_in[9];
    const float* nw1   = (const float*)d_in[10];
    const float* nb1   = (const float*)d_in[11];
    const float* nw2   = (const float*)d_in[12];
    const float* nb2   = (const float*)d_in[13];
    const float* lw    = (const float*)d_in[14];
    const float* lb    = (const float*)d_in[15];
    float* out = (float*)d_out;

    cudaFuncSetAttribute(gemm_hmma_kernel,
                         cudaFuncAttributeMaxDynamicSharedMemorySize, GEMM_SMEM);
    cudaFuncSetAttribute(combine_hmma_kernel,
                         cudaFuncAttributeMaxDynamicSharedMemorySize, CMB_SMEM);

    bc_kernel<<<1, 256>>>(w_ih, b_dr, b_ih);
    combine_hmma_kernel<<<Din / 128, 256, CMB_SMEM>>>(w_dr, w_ih);
    gemm_hmma_kernel<<<(Bsz * Tlen) / 64, 256, GEMM_SMEM>>>(x, x_len);
    gru_kernel<<<Bsz, 256>>>(w_hh, b_hh, w_reg, b_reg, x_len);
    pool_kernel<<<Bsz, 256>>>(x_len, nw1, nb1, nw2, nb2, lw, lb, out);
}